// round 16
// baseline (speedup 1.0000x reference)
#include <cuda_runtime.h>
#include <math.h>
#include <float.h>

#define BB 4
#define NN 8192
#define KK 20
#define EPSF 1e-6f
#define BN_EPSF 1e-5f

// ---------------- static device buffers (no allocation allowed) ----------------
__device__ float4 g_pts4[BB*NN];
__device__ int    g_idx[BB*NN*KK];
__device__ float  g_x1[BB*21*3*NN];
__device__ float  g_x2[BB*21*3*NN];
__device__ float  g_x3[BB*42*3*NN];
__device__ float  g_x4[BB*85*3*NN];
__device__ float  g_z1[BB*85*3*NN];
__device__ float  g_z2[BB*42*3*NN];
__device__ float  g_z3[BB*3*3*NN];
__device__ float  g_p [BB*85*3*NN];
__device__ float  g_d [BB*85*3*NN];
__device__ double g_stats[6*2*85];   // [layer][S1|S2][channel<=85]
__device__ float  g_bn[6*2*85];      // [layer][mean|istd][channel]
__device__ float  g_meanv[BB*85*3];
__device__ float  g_cf[BB*85*3];
__device__ float  g_cd[BB*85*3];

// ---------------- kernels ----------------

__global__ void zero_stats(){
    int i = blockIdx.x*blockDim.x + threadIdx.x;
    if (i < 6*2*85) g_stats[i] = 0.0;
}

// tiny filler so knn_kernel stays on the profiled launch slot
__global__ void zero_bn(){
    int i = blockIdx.x*blockDim.x + threadIdx.x;
    if (i < 6*2*85) g_bn[i] = 0.f;
}

// xx computed EXACTLY like XLA: elementwise squares, sequential adds, NO fma.
__global__ void pack_kernel(const float* __restrict__ pts){
    int i = blockIdx.x*blockDim.x + threadIdx.x;
    if (i >= BB*NN) return;
    float x = pts[i*3+0], y = pts[i*3+1], z = pts[i*3+2];
    float xx = __fadd_rn(__fadd_rn(__fmul_rn(x,x), __fmul_rn(y,y)), __fmul_rn(z,z));
    g_pts4[i] = make_float4(x, y, z, xx);
}

__device__ __forceinline__ void topk_insert20(float pd, int cand, float* val, int* idx){
    // sorted-desc insert, strict >, stable for equal values (earlier stays ahead)
    #pragma unroll
    for (int j = KK-1; j >= 0; j--){
        if (pd > val[j]){
            bool here = (j == 0) || !(pd > val[j-1]);
            val[j] = here ? pd : val[j-1];
            idx[j] = here ? cand : idx[j-1];
        }
    }
}

#define KNN_TILE 512
__global__ void __launch_bounds__(128) knn_kernel(){
    __shared__ float4 tile[KNN_TILE];
    int b = blockIdx.y;
    int q = blockIdx.x*128 + threadIdx.x;
    const float4* P = g_pts4 + b*NN;
    float4 me = P[q];
    float negxx = -me.w;
    float val[KK]; int idx[KK];
    #pragma unroll
    for (int j=0;j<KK;j++){ val[j] = -FLT_MAX; idx[j] = 0; }
    float worst = -FLT_MAX;

    for (int t0 = 0; t0 < NN; t0 += KNN_TILE){
        __syncthreads();
        #pragma unroll
        for (int j = threadIdx.x; j < KNN_TILE; j += 128) tile[j] = P[t0 + j];
        __syncthreads();
        #pragma unroll 4
        for (int jj = 0; jj < KNN_TILE; jj++){
            float4 c = tile[jj];
            float d  = __fmaf_rn(me.z, c.z, __fmaf_rn(me.y, c.y, __fmul_rn(me.x, c.x)));
            float pd = __fadd_rn(__fmaf_rn(2.0f, d, negxx), -c.w);
            if (pd > worst){
                topk_insert20(pd, t0 + jj, val, idx);
                worst = val[KK-1];
            }
        }
    }
    #pragma unroll
    for (int k=0;k<KK;k++) g_idx[(b*NN + q)*KK + k] = idx[k];
}

// layer 0 (pos) pass1: BN stats, channel-group split (3 groups of 7)
__global__ void __launch_bounds__(256) pos_pass1(const float* __restrict__ wf){
    __shared__ float wfs[63];
    __shared__ double sred[8][14];
    if (threadIdx.x < 63) wfs[threadIdx.x] = wf[threadIdx.x];
    __syncthreads();
    int og = blockIdx.y * 7;   // 0, 7, 14
    float s1[7], s2[7];
    #pragma unroll
    for (int oo=0;oo<7;oo++){ s1[oo]=0.f; s2[oo]=0.f; }
    int tidg = blockIdx.x*blockDim.x + threadIdx.x;
    int stride = gridDim.x*blockDim.x;
    for (int item = tidg; item < BB*NN*KK; item += stride){
        int bn = item / KK;
        int b  = bn >> 13;
        float4 ct = g_pts4[bn];
        float4 nb = g_pts4[b*NN + g_idx[item]];
        float rx = nb.x-ct.x, ry = nb.y-ct.y, rz = nb.z-ct.z;
        float cx = nb.y*ct.z - nb.z*ct.y;
        float cy = nb.z*ct.x - nb.x*ct.z;
        float cz = nb.x*ct.y - nb.y*ct.x;
        #pragma unroll
        for (int oo=0;oo<7;oo++){
            int o = og + oo;
            float w0=wfs[o*3], w1=wfs[o*3+1], w2=wfs[o*3+2];
            float p0 = w0*rx + w1*ct.x + w2*cx;
            float p1 = w0*ry + w1*ct.y + w2*cy;
            float p2 = w0*rz + w1*ct.z + w2*cz;
            float nrm = sqrtf(p0*p0 + p1*p1 + p2*p2) + EPSF;
            s1[oo] += nrm; s2[oo] += nrm*nrm;
        }
    }
    int wid = threadIdx.x >> 5, lid = threadIdx.x & 31;
    #pragma unroll
    for (int oo=0;oo<7;oo++){
        float a = s1[oo], c2 = s2[oo];
        #pragma unroll
        for (int off=16; off; off>>=1){
            a  += __shfl_xor_sync(0xffffffffu, a,  off);
            c2 += __shfl_xor_sync(0xffffffffu, c2, off);
        }
        if (lid == 0){ sred[wid][oo] = (double)a; sred[wid][7+oo] = (double)c2; }
    }
    __syncthreads();
    if (threadIdx.x < 14){
        double s = 0.0;
        #pragma unroll
        for (int w=0; w<8; w++) s += sred[w][threadIdx.x];
        int oo = (threadIdx.x < 7) ? threadIdx.x : (threadIdx.x - 7);
        int k = (threadIdx.x < 7) ? 0 : 85;
        atomicAdd(&g_stats[0*170 + k + og + oo], s);
    }
}

__global__ void bn_finalize(int layer, int C, double invcnt){
    int c = threadIdx.x;
    if (c < C){
        double m = g_stats[layer*170 + c] * invcnt;
        double v = g_stats[layer*170 + 85 + c] * invcnt - m*m;
        if (v < 0.0) v = 0.0;
        g_bn[layer*170 + c]      = (float)m;
        g_bn[layer*170 + 85 + c] = rsqrtf((float)v + BN_EPSF);
    }
}

// layer 0 (pos) pass2: BN + LLR + mean over K, channel-group split (7 groups of 3)
__global__ void __launch_bounds__(128) pos_pass2(const float* __restrict__ wf, const float* __restrict__ wd){
    __shared__ float wfs[63], wds[63], mns[21], isd[21];
    int t = threadIdx.x;
    if (t < 63){ wfs[t] = wf[t]; wds[t] = wd[t]; }
    if (t < 21){ mns[t] = g_bn[t]; isd[t] = g_bn[85+t]; }
    __syncthreads();
    int og = blockIdx.y * 3;          // 0,3,...,18
    int bn = blockIdx.x*128 + t;
    int b = bn >> 13;
    int n = bn & (NN-1);
    float4 ct = g_pts4[bn];
    float acc[3][3];
    #pragma unroll
    for (int oo=0;oo<3;oo++){ acc[oo][0]=0.f; acc[oo][1]=0.f; acc[oo][2]=0.f; }
    for (int k=0;k<KK;k++){
        float4 nb = g_pts4[b*NN + g_idx[bn*KK + k]];
        float rx = nb.x-ct.x, ry = nb.y-ct.y, rz = nb.z-ct.z;
        float cx = nb.y*ct.z - nb.z*ct.y;
        float cy = nb.z*ct.x - nb.x*ct.z;
        float cz = nb.x*ct.y - nb.y*ct.x;
        #pragma unroll
        for (int oo=0;oo<3;oo++){
            int o = og + oo;
            float w0=wfs[o*3], w1=wfs[o*3+1], w2=wfs[o*3+2];
            float p0 = w0*rx + w1*ct.x + w2*cx;
            float p1 = w0*ry + w1*ct.y + w2*cy;
            float p2 = w0*rz + w1*ct.z + w2*cz;
            float nrm = sqrtf(p0*p0 + p1*p1 + p2*p2) + EPSF;
            float f = (nrm - mns[o]) * isd[o] / nrm;
            p0 *= f; p1 *= f; p2 *= f;
            float v0=wds[o*3], v1=wds[o*3+1], v2=wds[o*3+2];
            float d0 = v0*rx + v1*ct.x + v2*cx;
            float d1 = v0*ry + v1*ct.y + v2*cy;
            float d2 = v0*rz + v1*ct.z + v2*cz;
            float dot = p0*d0 + p1*d1 + p2*d2;
            float e0, e1, e2;
            if (dot >= 0.f){ e0=p0; e1=p1; e2=p2; }
            else {
                float cc = dot / (d0*d0 + d1*d1 + d2*d2 + EPSF);
                e0 = p0 - cc*d0; e1 = p1 - cc*d1; e2 = p2 - cc*d2;
            }
            acc[oo][0] += e0; acc[oo][1] += e1; acc[oo][2] += e2;
        }
    }
    #pragma unroll
    for (int oo=0;oo<3;oo++){
        int o = og + oo;
        int base = ((b*21+o)*3)*NN + n;
        g_x1[base]      = acc[oo][0]*(1.0f/KK);
        g_x1[base+NN]   = acc[oo][1]*(1.0f/KK);
        g_x1[base+2*NN] = acc[oo][2]*(1.0f/KK);
    }
}

// fused dual GEMM: pf = Wf*X (+biasF), pd = Wd*X (+biasD); store both; BN stats on pf
template<int OGT>
__global__ void __launch_bounds__(128) lin_dual(const float* __restrict__ X, int Cin, int Cout,
                          const float* __restrict__ Wf, const float* __restrict__ Wd, int ldW,
                          const float* __restrict__ biasF, const float* __restrict__ biasD,
                          int layer,
                          float* __restrict__ pfout, float* __restrict__ pdout){
    __shared__ float Wfs[OGT][176];
    __shared__ float Wds[OGT][176];
    __shared__ double sred[4][OGT*2];
    int tid = threadIdx.x;
    int ob = blockIdx.y*OGT;
    int b  = blockIdx.z;
    for (int i = tid; i < OGT*Cin; i += 128){
        int g = i / Cin, c = i - g*Cin;
        int o = ob + g;
        Wfs[g][c] = (o < Cout) ? Wf[o*ldW + c] : 0.f;
        Wds[g][c] = (o < Cout) ? Wd[o*ldW + c] : 0.f;
    }
    __syncthreads();
    int n = blockIdx.x*128 + tid;
    float af[OGT][3], ad[OGT][3];
    #pragma unroll
    for (int g=0; g<OGT; g++){
        int o = ob + g;
        if (biasF != nullptr && o < Cout){
            af[g][0] = biasF[(b*Cout+o)*3+0];
            af[g][1] = biasF[(b*Cout+o)*3+1];
            af[g][2] = biasF[(b*Cout+o)*3+2];
            ad[g][0] = biasD[(b*Cout+o)*3+0];
            ad[g][1] = biasD[(b*Cout+o)*3+1];
            ad[g][2] = biasD[(b*Cout+o)*3+2];
        } else {
            af[g][0]=0.f; af[g][1]=0.f; af[g][2]=0.f;
            ad[g][0]=0.f; ad[g][1]=0.f; ad[g][2]=0.f;
        }
    }
    const float* Xb = X + (b*Cin)*3*NN + n;
    for (int c = 0; c < Cin; c++){
        float x0 = Xb[(c*3+0)*NN];
        float x1 = Xb[(c*3+1)*NN];
        float x2 = Xb[(c*3+2)*NN];
        #pragma unroll
        for (int g=0; g<OGT; g++){
            float wf = Wfs[g][c];
            af[g][0] = fmaf(wf, x0, af[g][0]);
            af[g][1] = fmaf(wf, x1, af[g][1]);
            af[g][2] = fmaf(wf, x2, af[g][2]);
            float wd = Wds[g][c];
            ad[g][0] = fmaf(wd, x0, ad[g][0]);
            ad[g][1] = fmaf(wd, x1, ad[g][1]);
            ad[g][2] = fmaf(wd, x2, ad[g][2]);
        }
    }
    int wid = tid >> 5, lid = tid & 31;
    #pragma unroll
    for (int g=0; g<OGT; g++){
        int o = ob + g;
        if (o >= Cout) continue;
        int base = ((b*Cout+o)*3)*NN + n;
        pfout[base]      = af[g][0];
        pfout[base+NN]   = af[g][1];
        pfout[base+2*NN] = af[g][2];
        pdout[base]      = ad[g][0];
        pdout[base+NN]   = ad[g][1];
        pdout[base+2*NN] = ad[g][2];
        float nrm = sqrtf(af[g][0]*af[g][0] + af[g][1]*af[g][1] + af[g][2]*af[g][2]) + EPSF;
        float s1 = nrm, s2 = nrm*nrm;
        #pragma unroll
        for (int off=16; off; off>>=1){
            s1 += __shfl_xor_sync(0xffffffffu, s1, off);
            s2 += __shfl_xor_sync(0xffffffffu, s2, off);
        }
        if (lid == 0){ sred[wid][g*2] = (double)s1; sred[wid][g*2+1] = (double)s2; }
    }
    __syncthreads();
    for (int t2 = tid; t2 < OGT*2; t2 += 128){
        int g = t2 >> 1, k = (t2 & 1) ? 85 : 0;
        int o = ob + g;
        if (o < Cout){
            double s = sred[0][t2] + sred[1][t2] + sred[2][t2] + sred[3][t2];
            atomicAdd(&g_stats[layer*170 + k + o], s);
        }
    }
}

// elementwise BN + LLR: read pf, pd -> Y
__global__ void llr_apply(int Cout, int layer,
                          const float* __restrict__ pf, const float* __restrict__ pd,
                          float* __restrict__ Y){
    int i = blockIdx.x*blockDim.x + threadIdx.x;
    if (i >= BB*85*NN) return;
    int n = i & (NN-1);
    int bo = i >> 13;
    if (bo >= BB*Cout) return;
    int o = bo % Cout;
    int base = bo*3*NN + n;
    float p0 = pf[base], p1 = pf[base+NN], p2 = pf[base+2*NN];
    float nrm = sqrtf(p0*p0 + p1*p1 + p2*p2) + EPSF;
    float f = (nrm - g_bn[layer*170+o]) * g_bn[layer*170+85+o] / nrm;
    p0 *= f; p1 *= f; p2 *= f;
    float d0 = pd[base], d1 = pd[base+NN], d2 = pd[base+2*NN];
    float dot = p0*d0 + p1*d1 + p2*d2;
    float e0, e1, e2;
    if (dot >= 0.f){ e0=p0; e1=p1; e2=p2; }
    else {
        float cc = dot / (d0*d0 + d1*d1 + d2*d2 + EPSF);
        e0 = p0 - cc*d0; e1 = p1 - cc*d1; e2 = p2 - cc*d2;
    }
    Y[base] = e0; Y[base+NN] = e1; Y[base+2*NN] = e2;
}

// single GEMM pass (layer 3): p = W*X, store p, BN stats
template<int OGT>
__global__ void __launch_bounds__(128) lin_pass1(const float* __restrict__ X, int Cin, int Cout,
                          const float* __restrict__ W, int ldW,
                          int layer, float* __restrict__ pout){
    __shared__ float Ws[OGT][176];
    __shared__ double sred[4][OGT*2];
    int tid = threadIdx.x;
    int ob = blockIdx.y*OGT;
    int b  = blockIdx.z;
    for (int i = tid; i < OGT*Cin; i += 128){
        int g = i / Cin, c = i - g*Cin;
        int o = ob + g;
        Ws[g][c] = (o < Cout) ? W[o*ldW + c] : 0.f;
    }
    __syncthreads();
    int n = blockIdx.x*128 + tid;
    float a[OGT][3];
    #pragma unroll
    for (int g=0; g<OGT; g++){ a[g][0]=0.f; a[g][1]=0.f; a[g][2]=0.f; }
    const float* Xb = X + (b*Cin)*3*NN + n;
    for (int c = 0; c < Cin; c++){
        float x0 = Xb[(c*3+0)*NN];
        float x1 = Xb[(c*3+1)*NN];
        float x2 = Xb[(c*3+2)*NN];
        #pragma unroll
        for (int g=0; g<OGT; g++){
            float w = Ws[g][c];
            a[g][0] = fmaf(w, x0, a[g][0]);
            a[g][1] = fmaf(w, x1, a[g][1]);
            a[g][2] = fmaf(w, x2, a[g][2]);
        }
    }
    int wid = tid >> 5, lid = tid & 31;
    #pragma unroll
    for (int g=0; g<OGT; g++){
        int o = ob + g;
        if (o >= Cout) continue;
        int base = ((b*Cout+o)*3)*NN + n;
        pout[base]      = a[g][0];
        pout[base+NN]   = a[g][1];
        pout[base+2*NN] = a[g][2];
        float nrm = sqrtf(a[g][0]*a[g][0] + a[g][1]*a[g][1] + a[g][2]*a[g][2]) + EPSF;
        float s1 = nrm, s2 = nrm*nrm;
        #pragma unroll
        for (int off=16; off; off>>=1){
            s1 += __shfl_xor_sync(0xffffffffu, s1, off);
            s2 += __shfl_xor_sync(0xffffffffu, s2, off);
        }
        if (lid == 0){ sred[wid][g*2] = (double)s1; sred[wid][g*2+1] = (double)s2; }
    }
    __syncthreads();
    for (int t2 = tid; t2 < OGT*2; t2 += 128){
        int g = t2 >> 1, k = (t2 & 1) ? 85 : 0;
        int o = ob + g;
        if (o < Cout){
            double s = sred[0][t2] + sred[1][t2] + sred[2][t2] + sred[3][t2];
            atomicAdd(&g_stats[layer*170 + k + o], s);
        }
    }
}

// w3 layer: BN-only apply (p -> x4)
__global__ void bn_apply_kernel(const float* __restrict__ pin, float* __restrict__ Y){
    int i = blockIdx.x*blockDim.x + threadIdx.x;
    if (i >= BB*85*NN) return;
    int n = i & (NN-1);
    int bo = i >> 13;
    int o = bo % 85;
    int base = bo*3*NN + n;
    float p0 = pin[base], p1 = pin[base+NN], p2 = pin[base+2*NN];
    float nrm = sqrtf(p0*p0 + p1*p1 + p2*p2) + EPSF;
    float f = (nrm - g_bn[3*170+o]) * g_bn[3*170+85+o] / nrm;
    Y[base] = p0*f; Y[base+NN] = p1*f; Y[base+2*NN] = p2*f;
}

// mean over N of x4 -> g_meanv ; also write x_mean_out and center_loc outputs
__global__ void mean_kernel(float* __restrict__ dout){
    int o = blockIdx.x, b = blockIdx.y, t = threadIdx.x;
    __shared__ float sm0[256], sm1[256], sm2[256];
    int base = ((b*85+o)*3)*NN;
    float s0=0.f, s1=0.f, s2=0.f;
    for (int n = t; n < NN; n += 256){
        s0 += g_x4[base+n]; s1 += g_x4[base+NN+n]; s2 += g_x4[base+2*NN+n];
    }
    sm0[t]=s0; sm1[t]=s1; sm2[t]=s2;
    __syncthreads();
    for (int s=128; s>0; s>>=1){
        if (t < s){ sm0[t]+=sm0[t+s]; sm1[t]+=sm1[t+s]; sm2[t]+=sm2[t+s]; }
        __syncthreads();
    }
    if (t == 0){
        float m0 = sm0[0]*(1.0f/NN), m1 = sm1[0]*(1.0f/NN), m2 = sm2[0]*(1.0f/NN);
        int mi = (b*85+o)*3;
        g_meanv[mi]=m0; g_meanv[mi+1]=m1; g_meanv[mi+2]=m2;
        dout[2040+mi]=m0; dout[2040+mi+1]=m1; dout[2040+mi+2]=m2;
        dout[3060 + b*85 + o] = (m0+m1+m2)*(1.0f/3.0f);
    }
}

// bias terms for ws1 layer (contribution of broadcast mean channels 85..169)
__global__ void cfcd_kernel(const float* __restrict__ ws1f, const float* __restrict__ ws1d){
    int i = blockIdx.x*blockDim.x + threadIdx.x;
    if (i >= BB*85*3) return;
    int d = i % 3;
    int bo = i / 3;
    int o = bo % 85;
    int b = bo / 85;
    float sf = 0.f, sd = 0.f;
    for (int c = 0; c < 85; c++){
        float m = g_meanv[(b*85+c)*3 + d];
        sf = fmaf(ws1f[o*170 + 85 + c], m, sf);
        sd = fmaf(ws1d[o*170 + 85 + c], m, sd);
    }
    g_cf[i] = sf; g_cd[i] = sd;
}

// z3 = wlin * z2  -> (B,3,3,N)
__global__ void wlin_kernel(const float* __restrict__ wlin){
    int bn = blockIdx.x*blockDim.x + threadIdx.x;
    if (bn >= BB*NN) return;
    int b = bn >> 13, n = bn & (NN-1);
    float acc[3][3];
    #pragma unroll
    for (int o=0;o<3;o++){ acc[o][0]=0.f; acc[o][1]=0.f; acc[o][2]=0.f; }
    for (int c = 0; c < 42; c++){
        float x0 = g_z2[((b*42+c)*3+0)*NN + n];
        float x1 = g_z2[((b*42+c)*3+1)*NN + n];
        float x2 = g_z2[((b*42+c)*3+2)*NN + n];
        #pragma unroll
        for (int o=0;o<3;o++){
            float w = wlin[o*42 + c];
            acc[o][0] = fmaf(w, x0, acc[o][0]);
            acc[o][1] = fmaf(w, x1, acc[o][1]);
            acc[o][2] = fmaf(w, x2, acc[o][2]);
        }
    }
    #pragma unroll
    for (int o=0;o<3;o++){
        #pragma unroll
        for (int d=0;d<3;d++){
            g_z3[((b*3+o)*3+d)*NN + n] = acc[o][d];
        }
    }
}

// inv_z: max over N of x_std[b,i,k,n] = sum_j x[b,i,j,n] * z_orig[b,k,j,n]
__global__ void final_kernel(float* __restrict__ dout){
    int i = blockIdx.x, b = blockIdx.y, t = threadIdx.x;
    __shared__ float sm0[256], sm1[256], sm2[256];
    float l0=-FLT_MAX, l1=-FLT_MAX, l2=-FLT_MAX;
    bool ism = (i >= 85);
    float c0=0.f, c1=0.f, c2=0.f;
    if (ism){
        int mbase = (b*85 + (i-85))*3;
        c0 = g_meanv[mbase]; c1 = g_meanv[mbase+1]; c2 = g_meanv[mbase+2];
    }
    int xbase = ism ? 0 : ((b*85+i)*3)*NN;
    int zb = b*9*NN;
    for (int n = t; n < NN; n += 256){
        float xj0, xj1, xj2;
        if (ism){ xj0=c0; xj1=c1; xj2=c2; }
        else { xj0 = g_x4[xbase+n]; xj1 = g_x4[xbase+NN+n]; xj2 = g_x4[xbase+2*NN+n]; }
        float s0 = xj0*g_z3[zb+0*NN+n] + xj1*g_z3[zb+1*NN+n] + xj2*g_z3[zb+2*NN+n];
        float s1 = xj0*g_z3[zb+3*NN+n] + xj1*g_z3[zb+4*NN+n] + xj2*g_z3[zb+5*NN+n];
        float s2 = xj0*g_z3[zb+6*NN+n] + xj1*g_z3[zb+7*NN+n] + xj2*g_z3[zb+8*NN+n];
        l0 = fmaxf(l0, s0); l1 = fmaxf(l1, s1); l2 = fmaxf(l2, s2);
    }
    sm0[t]=l0; sm1[t]=l1; sm2[t]=l2;
    __syncthreads();
    for (int s=128; s>0; s>>=1){
        if (t < s){
            sm0[t]=fmaxf(sm0[t],sm0[t+s]);
            sm1[t]=fmaxf(sm1[t],sm1[t+s]);
            sm2[t]=fmaxf(sm2[t],sm2[t+s]);
        }
        __syncthreads();
    }
    if (t == 0){
        int o = b*510 + i*3;
        dout[o]   = sm0[0];
        dout[o+1] = sm1[0];
        dout[o+2] = sm2[0];
    }
}

// ---------------- host launcher ----------------
extern "C" void kernel_launch(void* const* d_in, const int* in_sizes, int n_in,
                              void* d_out, int out_size){
    const float* points = (const float*)d_in[0];
    const float* wposf  = (const float*)d_in[1];
    const float* wposd  = (const float*)d_in[2];
    const float* w1f    = (const float*)d_in[3];
    const float* w1d    = (const float*)d_in[4];
    const float* w2f    = (const float*)d_in[5];
    const float* w2d    = (const float*)d_in[6];
    const float* w3     = (const float*)d_in[7];
    const float* ws1f   = (const float*)d_in[8];
    const float* ws1d   = (const float*)d_in[9];
    const float* ws2f   = (const float*)d_in[10];
    const float* ws2d   = (const float*)d_in[11];
    const float* wlin   = (const float*)d_in[12];
    float* out = (float*)d_out;

    float *x1, *x2, *x3, *x4, *z1, *z2, *p, *d, *cf, *cd;
    cudaGetSymbolAddress((void**)&x1, g_x1);
    cudaGetSymbolAddress((void**)&x2, g_x2);
    cudaGetSymbolAddress((void**)&x3, g_x3);
    cudaGetSymbolAddress((void**)&x4, g_x4);
    cudaGetSymbolAddress((void**)&z1, g_z1);
    cudaGetSymbolAddress((void**)&z2, g_z2);
    cudaGetSymbolAddress((void**)&p,  g_p);
    cudaGetSymbolAddress((void**)&d,  g_d);
    cudaGetSymbolAddress((void**)&cf, g_cf);
    cudaGetSymbolAddress((void**)&cd, g_cd);

    const double invBNK = 1.0 / ((double)BB*NN*KK);
    const double invBN  = 1.0 / ((double)BB*NN);

    zero_stats<<<3, 512>>>();
    pack_kernel<<<(BB*NN+255)/256, 256>>>(points);
    zero_bn<<<3, 512>>>();                       // filler so knn lands on the profiled slot
    knn_kernel<<<dim3(NN/128, BB), 128>>>();

    // layer 0: pos (feat 3 -> 21, per (b,n,k), then mean over K)
    pos_pass1<<<dim3(592, 3), 256>>>(wposf);
    bn_finalize<<<1, 96>>>(0, 21, invBNK);
    pos_pass2<<<dim3(BB*NN/128, 7), 128>>>(wposf, wposd);

    // grids: 21ch -> OG=11 (2 groups); 42ch -> OG=14 (3 groups); 85ch -> OG=15 (6 groups)
    dim3 g21(NN/128, 2, BB);
    dim3 g42(NN/128, 3, BB);
    dim3 g85(NN/128, 6, BB);
    int ew21 = (BB*21*NN+255)/256;
    int ew42 = (BB*42*NN+255)/256;
    int ew85 = (BB*85*NN+255)/256;

    // layer 1: w1 (21 -> 21)
    lin_dual<11><<<g21, 128>>>(x1, 21, 21, w1f, w1d, 21, nullptr, nullptr, 1, p, d);
    bn_finalize<<<1, 96>>>(1, 21, invBN);
    llr_apply<<<ew21, 256>>>(21, 1, p, d, x2);

    // layer 2: w2[:, :21] (21 -> 42)
    lin_dual<14><<<g42, 128>>>(x2, 21, 42, w2f, w2d, 42, nullptr, nullptr, 2, p, d);
    bn_finalize<<<1, 96>>>(2, 42, invBN);
    llr_apply<<<ew42, 256>>>(42, 2, p, d, x3);

    // layer 3: w3 linear + bn only (42 -> 85)
    lin_pass1<15><<<g85, 128>>>(x3, 42, 85, w3, 42, 3, p);
    bn_finalize<<<1, 96>>>(3, 85, invBN);
    bn_apply_kernel<<<ew85, 256>>>(p, x4);

    // mean over N (also writes x_mean_out and center_loc outputs)
    mean_kernel<<<dim3(85, BB), 256>>>(out);
    cfcd_kernel<<<(BB*85*3+127)/128, 128>>>(ws1f, ws1d);

    // layer 4: ws1 on concat [x4; broadcast mean] (170 -> 85) via bias trick
    lin_dual<15><<<g85, 128>>>(x4, 85, 85, ws1f, ws1d, 170, cf, cd, 4, p, d);
    bn_finalize<<<1, 96>>>(4, 85, invBN);
    llr_apply<<<ew85, 256>>>(85, 4, p, d, z1);

    // layer 5: ws2 (85 -> 42)
    lin_dual<14><<<g42, 128>>>(z1, 85, 42, ws2f, ws2d, 85, nullptr, nullptr, 5, p, d);
    bn_finalize<<<1, 96>>>(5, 42, invBN);
    llr_apply<<<ew42, 256>>>(42, 5, p, d, z2);

    // z3 = wlin * z2, then inv_z = max over N of x_std
    wlin_kernel<<<(BB*NN+127)/128, 128>>>(wlin);
    final_kernel<<<dim3(170, BB), 256>>>(out);
}

// round 17
// speedup vs baseline: 1.1233x; 1.1233x over previous
#include <cuda_runtime.h>
#include <math.h>
#include <float.h>

#define BB 4
#define NN 8192
#define KK 20
#define EPSF 1e-6f
#define BN_EPSF 1e-5f
#define OG 8

// ---------------- static device buffers (no allocation allowed) ----------------
__device__ float4 g_pts4[BB*NN];
__device__ int    g_idx[BB*NN*KK];
__device__ float  g_x1[BB*21*3*NN];
__device__ float  g_x2[BB*21*3*NN];
__device__ float  g_x3[BB*42*3*NN];
__device__ float  g_x4[BB*85*3*NN];
__device__ float  g_z1[BB*85*3*NN];
__device__ float  g_z2[BB*42*3*NN];
__device__ float  g_z3[BB*3*3*NN];
__device__ float  g_p [BB*85*3*NN];
__device__ float  g_d [BB*85*3*NN];
__device__ double g_stats[6*2*85];   // [layer][S1|S2][channel<=85]
__device__ float  g_bn[6*2*85];      // [layer][mean|istd][channel]
__device__ float  g_meanv[BB*85*3];
__device__ float  g_cf[BB*85*3];
__device__ float  g_cd[BB*85*3];

// ---------------- kernels ----------------

__global__ void zero_stats(){
    int i = blockIdx.x*blockDim.x + threadIdx.x;
    if (i < 6*2*85) g_stats[i] = 0.0;
}

// tiny filler so knn_kernel stays on the profiled launch slot
__global__ void zero_bn(){
    int i = blockIdx.x*blockDim.x + threadIdx.x;
    if (i < 6*2*85) g_bn[i] = 0.f;
}

// xx computed EXACTLY like XLA: elementwise squares, sequential adds, NO fma.
__global__ void pack_kernel(const float* __restrict__ pts){
    int i = blockIdx.x*blockDim.x + threadIdx.x;
    if (i >= BB*NN) return;
    float x = pts[i*3+0], y = pts[i*3+1], z = pts[i*3+2];
    float xx = __fadd_rn(__fadd_rn(__fmul_rn(x,x), __fmul_rn(y,y)), __fmul_rn(z,z));
    g_pts4[i] = make_float4(x, y, z, xx);
}

__device__ __forceinline__ void topk_insert20(float pd, int cand, float* val, int* idx){
    // sorted-desc insert, strict >, stable for equal values (earlier stays ahead)
    #pragma unroll
    for (int j = KK-1; j >= 0; j--){
        if (pd > val[j]){
            bool here = (j == 0) || !(pd > val[j-1]);
            val[j] = here ? pd : val[j-1];
            idx[j] = here ? cand : idx[j-1];
        }
    }
}

#define KNN_TILE 512
__global__ void __launch_bounds__(128) knn_kernel(){
    __shared__ float4 tile[KNN_TILE];
    int b = blockIdx.y;
    int q = blockIdx.x*128 + threadIdx.x;
    const float4* P = g_pts4 + b*NN;
    float4 me = P[q];
    float negxx = -me.w;
    float val[KK]; int idx[KK];
    #pragma unroll
    for (int j=0;j<KK;j++){ val[j] = -FLT_MAX; idx[j] = 0; }
    float worst = -FLT_MAX;

    for (int t0 = 0; t0 < NN; t0 += KNN_TILE){
        __syncthreads();
        #pragma unroll
        for (int j = threadIdx.x; j < KNN_TILE; j += 128) tile[j] = P[t0 + j];
        __syncthreads();
        #pragma unroll 4
        for (int jj = 0; jj < KNN_TILE; jj++){
            float4 c = tile[jj];
            float d  = __fmaf_rn(me.z, c.z, __fmaf_rn(me.y, c.y, __fmul_rn(me.x, c.x)));
            float pd = __fadd_rn(__fmaf_rn(2.0f, d, negxx), -c.w);
            if (pd > worst){
                topk_insert20(pd, t0 + jj, val, idx);
                worst = val[KK-1];
            }
        }
    }
    #pragma unroll
    for (int k=0;k<KK;k++) g_idx[(b*NN + q)*KK + k] = idx[k];
}

// layer 0 (pos) pass1: BN stats, channel-group split (3 groups of 7)
__global__ void __launch_bounds__(256) pos_pass1(const float* __restrict__ wf){
    __shared__ float wfs[63];
    __shared__ double sred[8][14];
    if (threadIdx.x < 63) wfs[threadIdx.x] = wf[threadIdx.x];
    __syncthreads();
    int og = blockIdx.y * 7;   // 0, 7, 14
    float s1[7], s2[7];
    #pragma unroll
    for (int oo=0;oo<7;oo++){ s1[oo]=0.f; s2[oo]=0.f; }
    int tidg = blockIdx.x*blockDim.x + threadIdx.x;
    int stride = gridDim.x*blockDim.x;
    for (int item = tidg; item < BB*NN*KK; item += stride){
        int bn = item / KK;
        int b  = bn >> 13;
        float4 ct = g_pts4[bn];
        float4 nb = g_pts4[b*NN + g_idx[item]];
        float rx = nb.x-ct.x, ry = nb.y-ct.y, rz = nb.z-ct.z;
        float cx = nb.y*ct.z - nb.z*ct.y;
        float cy = nb.z*ct.x - nb.x*ct.z;
        float cz = nb.x*ct.y - nb.y*ct.x;
        #pragma unroll
        for (int oo=0;oo<7;oo++){
            int o = og + oo;
            float w0=wfs[o*3], w1=wfs[o*3+1], w2=wfs[o*3+2];
            float p0 = w0*rx + w1*ct.x + w2*cx;
            float p1 = w0*ry + w1*ct.y + w2*cy;
            float p2 = w0*rz + w1*ct.z + w2*cz;
            float nrm = sqrtf(p0*p0 + p1*p1 + p2*p2) + EPSF;
            s1[oo] += nrm; s2[oo] += nrm*nrm;
        }
    }
    int wid = threadIdx.x >> 5, lid = threadIdx.x & 31;
    #pragma unroll
    for (int oo=0;oo<7;oo++){
        float a = s1[oo], c2 = s2[oo];
        #pragma unroll
        for (int off=16; off; off>>=1){
            a  += __shfl_xor_sync(0xffffffffu, a,  off);
            c2 += __shfl_xor_sync(0xffffffffu, c2, off);
        }
        if (lid == 0){ sred[wid][oo] = (double)a; sred[wid][7+oo] = (double)c2; }
    }
    __syncthreads();
    if (threadIdx.x < 14){
        double s = 0.0;
        #pragma unroll
        for (int w=0; w<8; w++) s += sred[w][threadIdx.x];
        int oo = (threadIdx.x < 7) ? threadIdx.x : (threadIdx.x - 7);
        int k = (threadIdx.x < 7) ? 0 : 85;
        atomicAdd(&g_stats[0*170 + k + og + oo], s);
    }
}

__global__ void bn_finalize(int layer, int C, double invcnt){
    int c = threadIdx.x;
    if (c < C){
        double m = g_stats[layer*170 + c] * invcnt;
        double v = g_stats[layer*170 + 85 + c] * invcnt - m*m;
        if (v < 0.0) v = 0.0;
        g_bn[layer*170 + c]      = (float)m;
        g_bn[layer*170 + 85 + c] = rsqrtf((float)v + BN_EPSF);
    }
}

// layer 0 (pos) pass2: BN + LLR + mean over K, channel-group split (7 groups of 3)
__global__ void __launch_bounds__(128) pos_pass2(const float* __restrict__ wf, const float* __restrict__ wd){
    __shared__ float wfs[63], wds[63], mns[21], isd[21];
    int t = threadIdx.x;
    if (t < 63){ wfs[t] = wf[t]; wds[t] = wd[t]; }
    if (t < 21){ mns[t] = g_bn[t]; isd[t] = g_bn[85+t]; }
    __syncthreads();
    int og = blockIdx.y * 3;          // 0,3,...,18
    int bn = blockIdx.x*128 + t;
    int b = bn >> 13;
    int n = bn & (NN-1);
    float4 ct = g_pts4[bn];
    float acc[3][3];
    #pragma unroll
    for (int oo=0;oo<3;oo++){ acc[oo][0]=0.f; acc[oo][1]=0.f; acc[oo][2]=0.f; }
    for (int k=0;k<KK;k++){
        float4 nb = g_pts4[b*NN + g_idx[bn*KK + k]];
        float rx = nb.x-ct.x, ry = nb.y-ct.y, rz = nb.z-ct.z;
        float cx = nb.y*ct.z - nb.z*ct.y;
        float cy = nb.z*ct.x - nb.x*ct.z;
        float cz = nb.x*ct.y - nb.y*ct.x;
        #pragma unroll
        for (int oo=0;oo<3;oo++){
            int o = og + oo;
            float w0=wfs[o*3], w1=wfs[o*3+1], w2=wfs[o*3+2];
            float p0 = w0*rx + w1*ct.x + w2*cx;
            float p1 = w0*ry + w1*ct.y + w2*cy;
            float p2 = w0*rz + w1*ct.z + w2*cz;
            float nrm = sqrtf(p0*p0 + p1*p1 + p2*p2) + EPSF;
            float f = (nrm - mns[o]) * isd[o] / nrm;
            p0 *= f; p1 *= f; p2 *= f;
            float v0=wds[o*3], v1=wds[o*3+1], v2=wds[o*3+2];
            float d0 = v0*rx + v1*ct.x + v2*cx;
            float d1 = v0*ry + v1*ct.y + v2*cy;
            float d2 = v0*rz + v1*ct.z + v2*cz;
            float dot = p0*d0 + p1*d1 + p2*d2;
            float e0, e1, e2;
            if (dot >= 0.f){ e0=p0; e1=p1; e2=p2; }
            else {
                float cc = dot / (d0*d0 + d1*d1 + d2*d2 + EPSF);
                e0 = p0 - cc*d0; e1 = p1 - cc*d1; e2 = p2 - cc*d2;
            }
            acc[oo][0] += e0; acc[oo][1] += e1; acc[oo][2] += e2;
        }
    }
    #pragma unroll
    for (int oo=0;oo<3;oo++){
        int o = og + oo;
        int base = ((b*21+o)*3)*NN + n;
        g_x1[base]      = acc[oo][0]*(1.0f/KK);
        g_x1[base+NN]   = acc[oo][1]*(1.0f/KK);
        g_x1[base+2*NN] = acc[oo][2]*(1.0f/KK);
    }
}

// fused dual GEMM: pf = Wf*X (+biasF), pd = Wd*X (+biasD); store both; BN stats on pf
template<int OGT>
__global__ void __launch_bounds__(128) lin_dual(const float* __restrict__ X, int Cin, int Cout,
                          const float* __restrict__ Wf, const float* __restrict__ Wd, int ldW,
                          const float* __restrict__ biasF, const float* __restrict__ biasD,
                          int layer,
                          float* __restrict__ pfout, float* __restrict__ pdout){
    __shared__ float Wfs[OGT][176];
    __shared__ float Wds[OGT][176];
    __shared__ double sred[4][OGT*2];
    int tid = threadIdx.x;
    int ob = blockIdx.y*OGT;
    int b  = blockIdx.z;
    for (int i = tid; i < OGT*Cin; i += 128){
        int g = i / Cin, c = i - g*Cin;
        int o = ob + g;
        Wfs[g][c] = (o < Cout) ? Wf[o*ldW + c] : 0.f;
        Wds[g][c] = (o < Cout) ? Wd[o*ldW + c] : 0.f;
    }
    __syncthreads();
    int n = blockIdx.x*128 + tid;
    float af[OGT][3], ad[OGT][3];
    #pragma unroll
    for (int g=0; g<OGT; g++){
        int o = ob + g;
        if (biasF != nullptr && o < Cout){
            af[g][0] = biasF[(b*Cout+o)*3+0];
            af[g][1] = biasF[(b*Cout+o)*3+1];
            af[g][2] = biasF[(b*Cout+o)*3+2];
            ad[g][0] = biasD[(b*Cout+o)*3+0];
            ad[g][1] = biasD[(b*Cout+o)*3+1];
            ad[g][2] = biasD[(b*Cout+o)*3+2];
        } else {
            af[g][0]=0.f; af[g][1]=0.f; af[g][2]=0.f;
            ad[g][0]=0.f; ad[g][1]=0.f; ad[g][2]=0.f;
        }
    }
    const float* Xb = X + (b*Cin)*3*NN + n;
    for (int c = 0; c < Cin; c++){
        float x0 = Xb[(c*3+0)*NN];
        float x1 = Xb[(c*3+1)*NN];
        float x2 = Xb[(c*3+2)*NN];
        #pragma unroll
        for (int g=0; g<OGT; g++){
            float wf = Wfs[g][c];
            af[g][0] = fmaf(wf, x0, af[g][0]);
            af[g][1] = fmaf(wf, x1, af[g][1]);
            af[g][2] = fmaf(wf, x2, af[g][2]);
            float wd = Wds[g][c];
            ad[g][0] = fmaf(wd, x0, ad[g][0]);
            ad[g][1] = fmaf(wd, x1, ad[g][1]);
            ad[g][2] = fmaf(wd, x2, ad[g][2]);
        }
    }
    int wid = tid >> 5, lid = tid & 31;
    #pragma unroll
    for (int g=0; g<OGT; g++){
        int o = ob + g;
        if (o >= Cout) continue;
        int base = ((b*Cout+o)*3)*NN + n;
        pfout[base]      = af[g][0];
        pfout[base+NN]   = af[g][1];
        pfout[base+2*NN] = af[g][2];
        pdout[base]      = ad[g][0];
        pdout[base+NN]   = ad[g][1];
        pdout[base+2*NN] = ad[g][2];
        float nrm = sqrtf(af[g][0]*af[g][0] + af[g][1]*af[g][1] + af[g][2]*af[g][2]) + EPSF;
        float s1 = nrm, s2 = nrm*nrm;
        #pragma unroll
        for (int off=16; off; off>>=1){
            s1 += __shfl_xor_sync(0xffffffffu, s1, off);
            s2 += __shfl_xor_sync(0xffffffffu, s2, off);
        }
        if (lid == 0){ sred[wid][g*2] = (double)s1; sred[wid][g*2+1] = (double)s2; }
    }
    __syncthreads();
    if (tid < OGT*2){
        int g = tid >> 1, k = (tid & 1) ? 85 : 0;
        int o = ob + g;
        if (o < Cout){
            double s = sred[0][tid] + sred[1][tid] + sred[2][tid] + sred[3][tid];
            atomicAdd(&g_stats[layer*170 + k + o], s);
        }
    }
}

// elementwise BN + LLR: read pf, pd -> Y
__global__ void llr_apply(int Cout, int layer,
                          const float* __restrict__ pf, const float* __restrict__ pd,
                          float* __restrict__ Y){
    int i = blockIdx.x*blockDim.x + threadIdx.x;
    if (i >= BB*85*NN) return;
    int n = i & (NN-1);
    int bo = i >> 13;
    if (bo >= BB*Cout) return;
    int o = bo % Cout;
    int base = bo*3*NN + n;
    float p0 = pf[base], p1 = pf[base+NN], p2 = pf[base+2*NN];
    float nrm = sqrtf(p0*p0 + p1*p1 + p2*p2) + EPSF;
    float f = (nrm - g_bn[layer*170+o]) * g_bn[layer*170+85+o] / nrm;
    p0 *= f; p1 *= f; p2 *= f;
    float d0 = pd[base], d1 = pd[base+NN], d2 = pd[base+2*NN];
    float dot = p0*d0 + p1*d1 + p2*d2;
    float e0, e1, e2;
    if (dot >= 0.f){ e0=p0; e1=p1; e2=p2; }
    else {
        float cc = dot / (d0*d0 + d1*d1 + d2*d2 + EPSF);
        e0 = p0 - cc*d0; e1 = p1 - cc*d1; e2 = p2 - cc*d2;
    }
    Y[base] = e0; Y[base+NN] = e1; Y[base+2*NN] = e2;
}

// single GEMM pass (layer 3): p = W*X, store p, BN stats
template<int OGT>
__global__ void __launch_bounds__(128) lin_pass1(const float* __restrict__ X, int Cin, int Cout,
                          const float* __restrict__ W, int ldW,
                          int layer, float* __restrict__ pout){
    __shared__ float Ws[OGT][176];
    __shared__ double sred[4][OGT*2];
    int tid = threadIdx.x;
    int ob = blockIdx.y*OGT;
    int b  = blockIdx.z;
    for (int i = tid; i < OGT*Cin; i += 128){
        int g = i / Cin, c = i - g*Cin;
        int o = ob + g;
        Ws[g][c] = (o < Cout) ? W[o*ldW + c] : 0.f;
    }
    __syncthreads();
    int n = blockIdx.x*128 + tid;
    float a[OGT][3];
    #pragma unroll
    for (int g=0; g<OGT; g++){ a[g][0]=0.f; a[g][1]=0.f; a[g][2]=0.f; }
    const float* Xb = X + (b*Cin)*3*NN + n;
    for (int c = 0; c < Cin; c++){
        float x0 = Xb[(c*3+0)*NN];
        float x1 = Xb[(c*3+1)*NN];
        float x2 = Xb[(c*3+2)*NN];
        #pragma unroll
        for (int g=0; g<OGT; g++){
            float w = Ws[g][c];
            a[g][0] = fmaf(w, x0, a[g][0]);
            a[g][1] = fmaf(w, x1, a[g][1]);
            a[g][2] = fmaf(w, x2, a[g][2]);
        }
    }
    int wid = tid >> 5, lid = tid & 31;
    #pragma unroll
    for (int g=0; g<OGT; g++){
        int o = ob + g;
        if (o >= Cout) continue;
        int base = ((b*Cout+o)*3)*NN + n;
        pout[base]      = a[g][0];
        pout[base+NN]   = a[g][1];
        pout[base+2*NN] = a[g][2];
        float nrm = sqrtf(a[g][0]*a[g][0] + a[g][1]*a[g][1] + a[g][2]*a[g][2]) + EPSF;
        float s1 = nrm, s2 = nrm*nrm;
        #pragma unroll
        for (int off=16; off; off>>=1){
            s1 += __shfl_xor_sync(0xffffffffu, s1, off);
            s2 += __shfl_xor_sync(0xffffffffu, s2, off);
        }
        if (lid == 0){ sred[wid][g*2] = (double)s1; sred[wid][g*2+1] = (double)s2; }
    }
    __syncthreads();
    if (tid < OGT*2){
        int g = tid >> 1, k = (tid & 1) ? 85 : 0;
        int o = ob + g;
        if (o < Cout){
            double s = sred[0][tid] + sred[1][tid] + sred[2][tid] + sred[3][tid];
            atomicAdd(&g_stats[layer*170 + k + o], s);
        }
    }
}

// w3 layer: BN-only apply (p -> x4)
__global__ void bn_apply_kernel(const float* __restrict__ pin, float* __restrict__ Y){
    int i = blockIdx.x*blockDim.x + threadIdx.x;
    if (i >= BB*85*NN) return;
    int n = i & (NN-1);
    int bo = i >> 13;
    int o = bo % 85;
    int base = bo*3*NN + n;
    float p0 = pin[base], p1 = pin[base+NN], p2 = pin[base+2*NN];
    float nrm = sqrtf(p0*p0 + p1*p1 + p2*p2) + EPSF;
    float f = (nrm - g_bn[3*170+o]) * g_bn[3*170+85+o] / nrm;
    Y[base] = p0*f; Y[base+NN] = p1*f; Y[base+2*NN] = p2*f;
}

// mean over N of x4 -> g_meanv ; also write x_mean_out and center_loc outputs
__global__ void mean_kernel(float* __restrict__ dout){
    int o = blockIdx.x, b = blockIdx.y, t = threadIdx.x;
    __shared__ float sm0[256], sm1[256], sm2[256];
    int base = ((b*85+o)*3)*NN;
    float s0=0.f, s1=0.f, s2=0.f;
    for (int n = t; n < NN; n += 256){
        s0 += g_x4[base+n]; s1 += g_x4[base+NN+n]; s2 += g_x4[base+2*NN+n];
    }
    sm0[t]=s0; sm1[t]=s1; sm2[t]=s2;
    __syncthreads();
    for (int s=128; s>0; s>>=1){
        if (t < s){ sm0[t]+=sm0[t+s]; sm1[t]+=sm1[t+s]; sm2[t]+=sm2[t+s]; }
        __syncthreads();
    }
    if (t == 0){
        float m0 = sm0[0]*(1.0f/NN), m1 = sm1[0]*(1.0f/NN), m2 = sm2[0]*(1.0f/NN);
        int mi = (b*85+o)*3;
        g_meanv[mi]=m0; g_meanv[mi+1]=m1; g_meanv[mi+2]=m2;
        dout[2040+mi]=m0; dout[2040+mi+1]=m1; dout[2040+mi+2]=m2;
        dout[3060 + b*85 + o] = (m0+m1+m2)*(1.0f/3.0f);
    }
}

// bias terms for ws1 layer (contribution of broadcast mean channels 85..169)
__global__ void cfcd_kernel(const float* __restrict__ ws1f, const float* __restrict__ ws1d){
    int i = blockIdx.x*blockDim.x + threadIdx.x;
    if (i >= BB*85*3) return;
    int d = i % 3;
    int bo = i / 3;
    int o = bo % 85;
    int b = bo / 85;
    float sf = 0.f, sd = 0.f;
    for (int c = 0; c < 85; c++){
        float m = g_meanv[(b*85+c)*3 + d];
        sf = fmaf(ws1f[o*170 + 85 + c], m, sf);
        sd = fmaf(ws1d[o*170 + 85 + c], m, sd);
    }
    g_cf[i] = sf; g_cd[i] = sd;
}

// z3 = wlin * z2  -> (B,3,3,N)
__global__ void wlin_kernel(const float* __restrict__ wlin){
    int bn = blockIdx.x*blockDim.x + threadIdx.x;
    if (bn >= BB*NN) return;
    int b = bn >> 13, n = bn & (NN-1);
    float acc[3][3];
    #pragma unroll
    for (int o=0;o<3;o++){ acc[o][0]=0.f; acc[o][1]=0.f; acc[o][2]=0.f; }
    for (int c = 0; c < 42; c++){
        float x0 = g_z2[((b*42+c)*3+0)*NN + n];
        float x1 = g_z2[((b*42+c)*3+1)*NN + n];
        float x2 = g_z2[((b*42+c)*3+2)*NN + n];
        #pragma unroll
        for (int o=0;o<3;o++){
            float w = wlin[o*42 + c];
            acc[o][0] = fmaf(w, x0, acc[o][0]);
            acc[o][1] = fmaf(w, x1, acc[o][1]);
            acc[o][2] = fmaf(w, x2, acc[o][2]);
        }
    }
    #pragma unroll
    for (int o=0;o<3;o++){
        #pragma unroll
        for (int d=0;d<3;d++){
            g_z3[((b*3+o)*3+d)*NN + n] = acc[o][d];
        }
    }
}

// inv_z: max over N of x_std[b,i,k,n] = sum_j x[b,i,j,n] * z_orig[b,k,j,n]
__global__ void final_kernel(float* __restrict__ dout){
    int i = blockIdx.x, b = blockIdx.y, t = threadIdx.x;
    __shared__ float sm0[256], sm1[256], sm2[256];
    float l0=-FLT_MAX, l1=-FLT_MAX, l2=-FLT_MAX;
    bool ism = (i >= 85);
    float c0=0.f, c1=0.f, c2=0.f;
    if (ism){
        int mbase = (b*85 + (i-85))*3;
        c0 = g_meanv[mbase]; c1 = g_meanv[mbase+1]; c2 = g_meanv[mbase+2];
    }
    int xbase = ism ? 0 : ((b*85+i)*3)*NN;
    int zb = b*9*NN;
    for (int n = t; n < NN; n += 256){
        float xj0, xj1, xj2;
        if (ism){ xj0=c0; xj1=c1; xj2=c2; }
        else { xj0 = g_x4[xbase+n]; xj1 = g_x4[xbase+NN+n]; xj2 = g_x4[xbase+2*NN+n]; }
        float s0 = xj0*g_z3[zb+0*NN+n] + xj1*g_z3[zb+1*NN+n] + xj2*g_z3[zb+2*NN+n];
        float s1 = xj0*g_z3[zb+3*NN+n] + xj1*g_z3[zb+4*NN+n] + xj2*g_z3[zb+5*NN+n];
        float s2 = xj0*g_z3[zb+6*NN+n] + xj1*g_z3[zb+7*NN+n] + xj2*g_z3[zb+8*NN+n];
        l0 = fmaxf(l0, s0); l1 = fmaxf(l1, s1); l2 = fmaxf(l2, s2);
    }
    sm0[t]=l0; sm1[t]=l1; sm2[t]=l2;
    __syncthreads();
    for (int s=128; s>0; s>>=1){
        if (t < s){
            sm0[t]=fmaxf(sm0[t],sm0[t+s]);
            sm1[t]=fmaxf(sm1[t],sm1[t+s]);
            sm2[t]=fmaxf(sm2[t],sm2[t+s]);
        }
        __syncthreads();
    }
    if (t == 0){
        int o = b*510 + i*3;
        dout[o]   = sm0[0];
        dout[o+1] = sm1[0];
        dout[o+2] = sm2[0];
    }
}

// ---------------- host launcher ----------------
extern "C" void kernel_launch(void* const* d_in, const int* in_sizes, int n_in,
                              void* d_out, int out_size){
    const float* points = (const float*)d_in[0];
    const float* wposf  = (const float*)d_in[1];
    const float* wposd  = (const float*)d_in[2];
    const float* w1f    = (const float*)d_in[3];
    const float* w1d    = (const float*)d_in[4];
    const float* w2f    = (const float*)d_in[5];
    const float* w2d    = (const float*)d_in[6];
    const float* w3     = (const float*)d_in[7];
    const float* ws1f   = (const float*)d_in[8];
    const float* ws1d   = (const float*)d_in[9];
    const float* ws2f   = (const float*)d_in[10];
    const float* ws2d   = (const float*)d_in[11];
    const float* wlin   = (const float*)d_in[12];
    float* out = (float*)d_out;

    float *x1, *x2, *x3, *x4, *z1, *z2, *p, *d, *cf, *cd;
    cudaGetSymbolAddress((void**)&x1, g_x1);
    cudaGetSymbolAddress((void**)&x2, g_x2);
    cudaGetSymbolAddress((void**)&x3, g_x3);
    cudaGetSymbolAddress((void**)&x4, g_x4);
    cudaGetSymbolAddress((void**)&z1, g_z1);
    cudaGetSymbolAddress((void**)&z2, g_z2);
    cudaGetSymbolAddress((void**)&p,  g_p);
    cudaGetSymbolAddress((void**)&d,  g_d);
    cudaGetSymbolAddress((void**)&cf, g_cf);
    cudaGetSymbolAddress((void**)&cd, g_cd);

    const double invBNK = 1.0 / ((double)BB*NN*KK);
    const double invBN  = 1.0 / ((double)BB*NN);

    zero_stats<<<3, 512>>>();
    pack_kernel<<<(BB*NN+255)/256, 256>>>(points);
    zero_bn<<<3, 512>>>();                       // filler so knn lands on the profiled slot
    knn_kernel<<<dim3(NN/128, BB), 128>>>();

    // layer 0: pos (feat 3 -> 21, per (b,n,k), then mean over K)
    pos_pass1<<<dim3(592, 3), 256>>>(wposf);
    bn_finalize<<<1, 96>>>(0, 21, invBNK);
    pos_pass2<<<dim3(BB*NN/128, 7), 128>>>(wposf, wposd);

    dim3 g21(NN/128, (21+OG-1)/OG, BB);
    dim3 g42(NN/128, (42+OG-1)/OG, BB);
    dim3 g85(NN/128, (85+OG-1)/OG, BB);
    int ew21 = (BB*21*NN+255)/256;
    int ew42 = (BB*42*NN+255)/256;
    int ew85 = (BB*85*NN+255)/256;

    // layer 1: w1 (21 -> 21)
    lin_dual<OG><<<g21, 128>>>(x1, 21, 21, w1f, w1d, 21, nullptr, nullptr, 1, p, d);
    bn_finalize<<<1, 96>>>(1, 21, invBN);
    llr_apply<<<ew21, 256>>>(21, 1, p, d, x2);

    // layer 2: w2[:, :21] (21 -> 42)
    lin_dual<OG><<<g42, 128>>>(x2, 21, 42, w2f, w2d, 42, nullptr, nullptr, 2, p, d);
    bn_finalize<<<1, 96>>>(2, 42, invBN);
    llr_apply<<<ew42, 256>>>(42, 2, p, d, x3);

    // layer 3: w3 linear + bn only (42 -> 85)
    lin_pass1<OG><<<g85, 128>>>(x3, 42, 85, w3, 42, 3, p);
    bn_finalize<<<1, 96>>>(3, 85, invBN);
    bn_apply_kernel<<<ew85, 256>>>(p, x4);

    // mean over N (also writes x_mean_out and center_loc outputs)
    mean_kernel<<<dim3(85, BB), 256>>>(out);
    cfcd_kernel<<<(BB*85*3+127)/128, 128>>>(ws1f, ws1d);

    // layer 4: ws1 on concat [x4; broadcast mean] (170 -> 85) via bias trick
    lin_dual<OG><<<g85, 128>>>(x4, 85, 85, ws1f, ws1d, 170, cf, cd, 4, p, d);
    bn_finalize<<<1, 96>>>(4, 85, invBN);
    llr_apply<<<ew85, 256>>>(85, 4, p, d, z1);

    // layer 5: ws2 (85 -> 42)
    lin_dual<OG><<<g42, 128>>>(z1, 85, 42, ws2f, ws2d, 85, nullptr, nullptr, 5, p, d);
    bn_finalize<<<1, 96>>>(5, 42, invBN);
    llr_apply<<<ew42, 256>>>(42, 5, p, d, z2);

    // z3 = wlin * z2, then inv_z = max over N of x_std
    wlin_kernel<<<(BB*NN+127)/128, 128>>>(wlin);
    final_kernel<<<dim3(170, BB), 256>>>(out);
}